// round 1
// baseline (speedup 1.0000x reference)
#include <cuda_runtime.h>
#include <cuda_bf16.h>
#include <math_constants.h>

#define E 512
#define L 1024
#define B2 512

__device__ float g_v[E];
__device__ float g_c;

// ---------------------------------------------------------------------------
// Prep: v[e] = sum_f W[f,e] * wv[f];  c = sum_f b[f] * wv[f]
// One block, E threads. Reads 1 MB of W — negligible.
// ---------------------------------------------------------------------------
__global__ void prep_kernel(const float* __restrict__ W,
                            const float* __restrict__ bias,
                            const float* __restrict__ wv) {
    __shared__ float s_wv[E];
    __shared__ float s_red[32];
    int e = threadIdx.x;
    s_wv[e] = wv[e];
    __syncthreads();

    float acc = 0.f;
    #pragma unroll 8
    for (int f = 0; f < E; ++f)
        acc = fmaf(W[f * E + e], s_wv[f], acc);
    g_v[e] = acc;

    // c = b . wv  (block reduce)
    float part = bias[e] * s_wv[e];
    #pragma unroll
    for (int o = 16; o; o >>= 1)
        part += __shfl_down_sync(0xffffffffu, part, o);
    int warp = e >> 5, lane = e & 31;
    if (lane == 0) s_red[warp] = part;
    __syncthreads();
    if (warp == 0) {
        float s = (lane < (E / 32)) ? s_red[lane] : 0.f;
        #pragma unroll
        for (int o = 16; o; o >>= 1)
            s += __shfl_down_sync(0xffffffffu, s, o);
        if (lane == 0) g_c = s;
    }
}

// ---------------------------------------------------------------------------
// Main: scores[b,l] = q[b,l,:] . v + c for l < len; softmax over valid prefix.
// One CTA per batch row; one warp per token; only valid tokens are read.
// ---------------------------------------------------------------------------
__global__ __launch_bounds__(1024, 2)
void attn_kernel(const float* __restrict__ q,
                 const int* __restrict__ lens,
                 float* __restrict__ out) {
    __shared__ float s_v[E];
    __shared__ float s_scores[L];
    __shared__ float s_red[32];
    __shared__ float s_bcast;

    const int tid  = threadIdx.x;
    const int warp = tid >> 5;
    const int lane = tid & 31;
    const int b    = blockIdx.x;
    const int len  = lens[b];

    // stage v into shared
    if (tid < E) s_v[tid] = g_v[tid];
    __syncthreads();

    const float c = g_c;
    const float4* __restrict__ vv = reinterpret_cast<const float4*>(s_v);
    const float* __restrict__ qrow = q + (size_t)b * L * E;

    // one warp per token, striding over valid tokens only
    for (int l = warp; l < len; l += 32) {
        const float4* __restrict__ qp =
            reinterpret_cast<const float4*>(qrow + (size_t)l * E);
        float acc = 0.f;
        #pragma unroll
        for (int k = 0; k < 4; ++k) {
            float4 a = __ldg(qp + k * 32 + lane);
            float4 w = vv[k * 32 + lane];
            acc = fmaf(a.x, w.x, acc);
            acc = fmaf(a.y, w.y, acc);
            acc = fmaf(a.z, w.z, acc);
            acc = fmaf(a.w, w.w, acc);
        }
        #pragma unroll
        for (int o = 16; o; o >>= 1)
            acc += __shfl_down_sync(0xffffffffu, acc, o);
        if (lane == 0) s_scores[l] = acc + c;
    }
    __syncthreads();

    // ---- softmax over [0, len) ----
    float val = (tid < len) ? s_scores[tid] : -CUDART_INF_F;

    // block max
    float m = val;
    #pragma unroll
    for (int o = 16; o; o >>= 1)
        m = fmaxf(m, __shfl_down_sync(0xffffffffu, m, o));
    if (lane == 0) s_red[warp] = m;
    __syncthreads();
    if (warp == 0) {
        float t = (lane < 32) ? s_red[lane] : -CUDART_INF_F;
        #pragma unroll
        for (int o = 16; o; o >>= 1)
            t = fmaxf(t, __shfl_down_sync(0xffffffffu, t, o));
        if (lane == 0) s_bcast = t;
    }
    __syncthreads();
    const float rowmax = s_bcast;

    float e = (tid < len) ? expf(val - rowmax) : 0.f;

    // block sum
    float s = e;
    #pragma unroll
    for (int o = 16; o; o >>= 1)
        s += __shfl_down_sync(0xffffffffu, s, o);
    __syncthreads();          // s_red reuse
    if (lane == 0) s_red[warp] = s;
    __syncthreads();
    if (warp == 0) {
        float t = (lane < 32) ? s_red[lane] : 0.f;
        #pragma unroll
        for (int o = 16; o; o >>= 1)
            t += __shfl_down_sync(0xffffffffu, t, o);
        if (lane == 0) s_bcast = t;
    }
    __syncthreads();

    out[(size_t)b * L + tid] = e / s_bcast;
}

extern "C" void kernel_launch(void* const* d_in, const int* in_sizes, int n_in,
                              void* d_out, int out_size) {
    const float* questions = (const float*)d_in[0];   // [B2, L, E]
    const int*   lens      = (const int*)d_in[1];     // [B2]
    const float* W         = (const float*)d_in[2];   // [E, E]
    const float* bias      = (const float*)d_in[3];   // [E]
    const float* wv        = (const float*)d_in[4];   // [E, 1]
    float* out             = (float*)d_out;           // [B2, L]

    prep_kernel<<<1, E>>>(W, bias, wv);
    attn_kernel<<<B2, 1024>>>(questions, lens, out);
}

// round 2
// speedup vs baseline: 1.3684x; 1.3684x over previous
#include <cuda_runtime.h>
#include <cuda_bf16.h>
#include <math_constants.h>

#define E 512
#define L 1024
#define B2 512

__device__ float g_v[E];
__device__ float g_c;
__device__ float g_scores[B2 * L];   // scratch: raw attention energies

// ---------------------------------------------------------------------------
// Prep: v[e] = sum_f W[f,e] * wv[f];  c = sum_f b[f] * wv[f]
// 512 blocks (one per output column e), 128 threads striding over f.
// ---------------------------------------------------------------------------
__global__ __launch_bounds__(128)
void prep_kernel(const float* __restrict__ W,
                 const float* __restrict__ bias,
                 const float* __restrict__ wv) {
    __shared__ float s_wv[E];
    __shared__ float s_red[4];
    const int t    = threadIdx.x;
    const int e    = blockIdx.x;
    const int warp = t >> 5, lane = t & 31;

    #pragma unroll
    for (int i = t; i < E; i += 128) s_wv[i] = wv[i];
    __syncthreads();

    float acc = 0.f;
    #pragma unroll
    for (int f = t; f < E; f += 128)
        acc = fmaf(W[f * E + e], s_wv[f], acc);

    #pragma unroll
    for (int o = 16; o; o >>= 1)
        acc += __shfl_down_sync(0xffffffffu, acc, o);
    if (lane == 0) s_red[warp] = acc;
    __syncthreads();
    if (t == 0)
        g_v[e] = s_red[0] + s_red[1] + s_red[2] + s_red[3];

    if (e == 0) {
        // c = bias . wv
        float part = 0.f;
        #pragma unroll
        for (int f = t; f < E; f += 128)
            part = fmaf(bias[f], s_wv[f], part);
        #pragma unroll
        for (int o = 16; o; o >>= 1)
            part += __shfl_down_sync(0xffffffffu, part, o);
        __syncthreads();
        if (lane == 0) s_red[warp] = part;
        __syncthreads();
        if (t == 0)
            g_c = s_red[0] + s_red[1] + s_red[2] + s_red[3];
    }
}

// ---------------------------------------------------------------------------
// Scores: fine-grained over (batch, 128-token chunk) for load balance.
// grid = (L/128, B2), 256 threads = 8 warps, 16 tokens/warp.
// scores[b,l] = q[b,l,:] . v + c  for l < len, into g_scores.
// ---------------------------------------------------------------------------
#define CHUNK 128
__global__ __launch_bounds__(256)
void scores_kernel(const float* __restrict__ q,
                   const int* __restrict__ lens) {
    __shared__ float s_v[E];

    const int tid  = threadIdx.x;
    const int warp = tid >> 5;
    const int lane = tid & 31;
    const int b    = blockIdx.y;
    const int base = blockIdx.x * CHUNK;
    const int len  = lens[b];

    if (base >= len) return;                 // whole chunk masked out

    #pragma unroll
    for (int i = tid; i < E; i += 256) s_v[i] = g_v[i];
    __syncthreads();

    const float c = g_c;
    const float4* __restrict__ vv = reinterpret_cast<const float4*>(s_v);
    const float*  __restrict__ qrow = q + (size_t)b * L * E;
    const int tok_end = min(base + CHUNK, len);

    // warp w owns tokens [base + w*16, base + w*16 + 16)
    for (int l = base + warp * 16; l < min(base + warp * 16 + 16, tok_end); ++l) {
        const float4* __restrict__ qp =
            reinterpret_cast<const float4*>(qrow + (size_t)l * E);
        float acc = 0.f;
        #pragma unroll
        for (int k = 0; k < 4; ++k) {
            float4 a = __ldg(qp + k * 32 + lane);
            float4 w = vv[k * 32 + lane];
            acc = fmaf(a.x, w.x, acc);
            acc = fmaf(a.y, w.y, acc);
            acc = fmaf(a.z, w.z, acc);
            acc = fmaf(a.w, w.w, acc);
        }
        #pragma unroll
        for (int o = 16; o; o >>= 1)
            acc += __shfl_down_sync(0xffffffffu, acc, o);
        if (lane == 0) g_scores[b * L + l] = acc + c;
    }
}

// ---------------------------------------------------------------------------
// Softmax over the valid prefix of each row. 512 blocks x 1024 threads.
// ---------------------------------------------------------------------------
__global__ __launch_bounds__(1024)
void softmax_kernel(const int* __restrict__ lens,
                    float* __restrict__ out) {
    __shared__ float s_red[32];
    __shared__ float s_bcast;

    const int tid  = threadIdx.x;
    const int warp = tid >> 5;
    const int lane = tid & 31;
    const int b    = blockIdx.x;
    const int len  = lens[b];

    float val = (tid < len) ? g_scores[b * L + tid] : -CUDART_INF_F;

    // block max
    float m = val;
    #pragma unroll
    for (int o = 16; o; o >>= 1)
        m = fmaxf(m, __shfl_down_sync(0xffffffffu, m, o));
    if (lane == 0) s_red[warp] = m;
    __syncthreads();
    if (warp == 0) {
        float t = s_red[lane];
        #pragma unroll
        for (int o = 16; o; o >>= 1)
            t = fmaxf(t, __shfl_down_sync(0xffffffffu, t, o));
        if (lane == 0) s_bcast = t;
    }
    __syncthreads();
    const float rowmax = s_bcast;

    float e = (tid < len) ? expf(val - rowmax) : 0.f;

    // block sum
    float s = e;
    #pragma unroll
    for (int o = 16; o; o >>= 1)
        s += __shfl_down_sync(0xffffffffu, s, o);
    __syncthreads();
    if (lane == 0) s_red[warp] = s;
    __syncthreads();
    if (warp == 0) {
        float t = s_red[lane];
        #pragma unroll
        for (int o = 16; o; o >>= 1)
            t += __shfl_down_sync(0xffffffffu, t, o);
        if (lane == 0) s_bcast = t;
    }
    __syncthreads();

    out[(size_t)b * L + tid] = e / s_bcast;
}

extern "C" void kernel_launch(void* const* d_in, const int* in_sizes, int n_in,
                              void* d_out, int out_size) {
    const float* questions = (const float*)d_in[0];   // [B2, L, E]
    const int*   lens      = (const int*)d_in[1];     // [B2]
    const float* W         = (const float*)d_in[2];   // [E, E]
    const float* bias      = (const float*)d_in[3];   // [E]
    const float* wv        = (const float*)d_in[4];   // [E, 1]
    float* out             = (float*)d_out;           // [B2, L]

    prep_kernel<<<E, 128>>>(W, bias, wv);
    dim3 sgrid(L / CHUNK, B2);
    scores_kernel<<<sgrid, 256>>>(questions, lens);
    softmax_kernel<<<B2, 1024>>>(lens, out);
}